// round 13
// baseline (speedup 1.0000x reference)
#include <cuda_runtime.h>

#define N_NODES 50000
#define N_EDGES 600000
#define N_MOL   512
#define NF      30

// ---------------- scratch (device globals; no allocation) ----------------
// h layout per node (3 x float4 = 12 floats): [m0..m3][m4..m7][m8, deg, 0, 0]
__device__ float4 g_h4[(size_t)N_NODES * 3];
// packed node data (2 x float4): [px,py,pz,b0][b1,b2,0,0]
__device__ float4 g_nd[(size_t)N_NODES * 2];
__device__ float  g_w[N_EDGES];          // edge_attr[:,0] compacted (written by scatter)
__device__ float  g_nodesum[N_NODES];
__device__ float  g_acc[N_MOL];
__device__ float  g_atoms[N_MOL];

#define NODE_BLOCKS ((N_NODES + 255) / 256)
#define PREP_ITEMS  (N_NODES * 3)                 // largest zero range
#define PREP_BLOCKS ((PREP_ITEMS + 255) / 256)

__device__ __forceinline__ void atomic_add_f4(float4* p, float4 v) {
#if defined(__CUDA_ARCH__) && (__CUDA_ARCH__ >= 900)
    atomicAdd(p, v);
#else
    float* s = (float*)p;
    atomicAdd(s + 0, v.x);
    atomicAdd(s + 1, v.y);
    atomicAdd(s + 2, v.z);
    atomicAdd(s + 3, v.w);
#endif
}

__device__ __forceinline__ float inv_sqrt_deg(float d) {
    return (d > 0.0f) ? rsqrtf(fmaxf(d, 1.0f)) : 0.0f;
}

__device__ __forceinline__ void compute_ea(float x, float y, float z, float w, float* ea) {
    const float s3  = 1.7320508075688772f;
    const float s5  = 2.2360679774997896f;
    const float s15 = 3.8729833462074170f;
    float r2 = x * x + y * y + z * z;
    ea[0] = w;
    ea[1] = w * s3 * x;
    ea[2] = w * s3 * y;
    ea[3] = w * s3 * z;
    ea[4] = w * s15 * x * y;
    ea[5] = w * s15 * y * z;
    ea[6] = w * 0.5f * s5 * (3.0f * z * z - r2);
    ea[7] = w * s15 * x * z;
    ea[8] = w * 0.5f * s15 * (x * x - y * y);
}

// ---------------- kernel 0 (prep): zero + b = x@V + pos pack (node-scale only) ----------------
__global__ void k_prep(const float* __restrict__ x,
                       const float* __restrict__ pos,
                       const float* __restrict__ W1_0,
                       const float* __restrict__ W1_1,
                       const float* __restrict__ W1_2,
                       const float* __restrict__ W2_0,
                       const float* __restrict__ W2_1,
                       const float* __restrict__ W2_2) {
    __shared__ float sV[3 * NF];
    int t = threadIdx.x;
    int i = blockIdx.x * blockDim.x + t;

    // V = (W1_l @ W2_l)/sqrt(30), only in blocks that will compute b
    if (blockIdx.x < NODE_BLOCKS) {
        const float inv_s30 = 0.18257418583505536f;
        if (t < NF) {
            float acc = 0.0f;
            #pragma unroll
            for (int u = 0; u < 64; u++) acc = fmaf(W1_0[t * 64 + u], W2_0[u], acc);
            sV[t] = acc * inv_s30;
        } else if (t < 2 * NF) {
            int k = t - NF;
            float acc = 0.0f;
            #pragma unroll
            for (int u = 0; u < 24; u++) acc = fmaf(W1_1[k * 24 + u], W2_1[u], acc);
            sV[t] = acc * inv_s30;
        } else if (t < 3 * NF) {
            int k = t - 2 * NF;
            float acc = 0.0f;
            #pragma unroll
            for (int u = 0; u < 16; u++) acc = fmaf(W1_2[k * 16 + u], W2_2[u], acc);
            sV[t] = acc * inv_s30;
        }
        __syncthreads();
    }

    // zero scratch (each array accumulated only in LATER kernels — race-free)
    if (i < N_NODES * 3) g_h4[i] = make_float4(0.f, 0.f, 0.f, 0.f);
    if (i < N_NODES) g_nodesum[i] = 0.0f;
    if (i < N_MOL)  { g_acc[i] = 0.0f; g_atoms[i] = 0.0f; }

    if (i < N_NODES) {
        // b = x @ V, packed with position
        const float* xr = x + (size_t)i * NF;
        float b0 = 0.0f, b1 = 0.0f, b2 = 0.0f;
        #pragma unroll
        for (int k = 0; k < NF; k++) {
            float xv = xr[k];
            b0 = fmaf(xv, sV[k], b0);
            b1 = fmaf(xv, sV[NF + k], b1);
            b2 = fmaf(xv, sV[2 * NF + k], b2);
        }
        float px = pos[i * 3 + 0];
        float py = pos[i * 3 + 1];
        float pz = pos[i * 3 + 2];
        g_nd[(size_t)i * 2 + 0] = make_float4(px, py, pz, b0);
        g_nd[(size_t)i * 2 + 1] = make_float4(b1, b2, 0.f, 0.f);
    }
}

// ---------------- kernel 1: edge scatter (w-extract folded in; 3 float4 atomics per edge) ------
__global__ void k_scatter(const float* __restrict__ eattr,
                          const int* __restrict__ esrc,
                          const int* __restrict__ edst) {
    int e = blockIdx.x * blockDim.x + threadIdx.x;
    if (e >= N_EDGES) return;
    int src = esrc[e];
    int dst = edst[e];
    // strided DRAM read hides under the atomic serialization below
    float w = __ldcs(eattr + (size_t)e * 10);
    g_w[e] = w;                       // compact for gather
    float4 s0 = g_nd[(size_t)src * 2 + 0];
    float4 s1 = g_nd[(size_t)src * 2 + 1];
    float4 d0 = g_nd[(size_t)dst * 2 + 0];
    float vx = s0.x - d0.x, vy = s0.y - d0.y, vz = s0.z - d0.z;
    float ea[9];
    compute_ea(vx, vy, vz, w, ea);
    float b0 = s0.w, b1 = s1.x, b2 = s1.y;
    float4* hp = g_h4 + (size_t)dst * 3;
    atomic_add_f4(hp + 0, make_float4(b0 * ea[0], b1 * ea[1], b1 * ea[2], b1 * ea[3]));
    atomic_add_f4(hp + 1, make_float4(b2 * ea[4], b2 * ea[5], b2 * ea[6], b2 * ea[7]));
    atomic_add_f4(hp + 2, make_float4(b2 * ea[8], 1.0f, 0.f, 0.f));
}

// ---------------- kernel 2: edge gather + contraction (isd_src AND isd_dst applied here) --------
__global__ void k_gather(const int* __restrict__ esrc,
                         const int* __restrict__ edst) {
    int e = blockIdx.x * blockDim.x + threadIdx.x;
    if (e >= N_EDGES) return;
    int src = esrc[e];
    int dst = edst[e];
    float4 s0 = g_nd[(size_t)src * 2 + 0];
    float4 d0 = g_nd[(size_t)dst * 2 + 0];
    float vx = s0.x - d0.x, vy = s0.y - d0.y, vz = s0.z - d0.z;
    float w = g_w[e];
    float ea[9];
    compute_ea(vx, vy, vz, w, ea);

    float4 h0 = g_h4[(size_t)src * 3 + 0];
    float4 h1 = g_h4[(size_t)src * 3 + 1];
    float4 h2 = g_h4[(size_t)src * 3 + 2];
    float isd_src = inv_sqrt_deg(h2.y);
    float isd_dst = inv_sqrt_deg(g_h4[(size_t)dst * 3 + 2].y);

    const float inv_s3 = 0.5773502691896258f;
    const float inv_s5 = 0.4472135954999579f;

    float t0 = h0.x * ea[0];
    float t1 = h0.y * ea[1] + h0.z * ea[2] + h0.w * ea[3];
    float t2 = h1.x * ea[4] + h1.y * ea[5] + h1.z * ea[6]
             + h1.w * ea[7] + h2.x * ea[8];
    float out_e = (t0 + t1 * inv_s3 + t2 * inv_s5) * isd_src * isd_dst * 0.09805806756909202f;
    atomicAdd(&g_nodesum[dst], out_e);   // 50k addresses — safe rate
}

// ---------------- kernel 3: node -> molecule (coalesced streams; warp-segmented; no fence) -----
__global__ void k_node_to_mol(const int* __restrict__ batch) {
    int i = blockIdx.x * blockDim.x + threadIdx.x;
    int lane = threadIdx.x & 31;
    bool valid = (i < N_NODES);
    int m = valid ? batch[i] : -1;
    float v = valid ? g_nodesum[i] : 0.0f;   // already scaled by isd[dst] in gather
    float c = valid ? 1.0f : 0.0f;
    // segmented suffix-sum over contiguous equal-m runs (batch sorted)
    #pragma unroll
    for (int off = 1; off < 32; off <<= 1) {
        float nv = __shfl_down_sync(0xFFFFFFFFu, v, off);
        float nc = __shfl_down_sync(0xFFFFFFFFu, c, off);
        int   nm = __shfl_down_sync(0xFFFFFFFFu, m, off);
        if (lane + off < 32 && nm == m) { v += nv; c += nc; }
    }
    int pm = __shfl_up_sync(0xFFFFFFFFu, m, 1);
    bool head = valid && (lane == 0 || pm != m);
    if (head) {
        atomicAdd(&g_acc[m], v);
        atomicAdd(&g_atoms[m], c);
    }
}

// ---------------- kernel 4: finalize ----------------
__global__ void k_finalize(float* __restrict__ out) {
    int m = threadIdx.x;
    if (m < N_MOL) {
        float a = g_atoms[m];
        out[m] = g_acc[m] * ((a > 0.0f) ? rsqrtf(fmaxf(a, 1.0f)) : 0.0f);
    }
}

// ---------------- launch ----------------
extern "C" void kernel_launch(void* const* d_in, const int* in_sizes, int n_in,
                              void* d_out, int out_size) {
    (void)in_sizes; (void)n_in; (void)out_size;
    const float* pos   = (const float*)d_in[0];
    const float* x     = (const float*)d_in[1];
    const float* eattr = (const float*)d_in[2];
    const float* W1_0  = (const float*)d_in[3];
    const float* W1_1  = (const float*)d_in[4];
    const float* W1_2  = (const float*)d_in[5];
    const float* W2_0  = (const float*)d_in[6];
    const float* W2_1  = (const float*)d_in[7];
    const float* W2_2  = (const float*)d_in[8];
    const int* esrc    = (const int*)d_in[9];
    const int* edst    = (const int*)d_in[10];
    const int* batch   = (const int*)d_in[11];
    float* out = (float*)d_out;

    int eblocks = (N_EDGES + 255) / 256;
    k_prep<<<PREP_BLOCKS, 256>>>(x, pos, W1_0, W1_1, W1_2, W2_0, W2_1, W2_2);
    k_scatter<<<eblocks, 256>>>(eattr, esrc, edst);
    k_gather<<<eblocks, 256>>>(esrc, edst);
    k_node_to_mol<<<(N_NODES + 255) / 256, 256>>>(batch);
    k_finalize<<<1, N_MOL>>>(out);
}

// round 14
// speedup vs baseline: 1.0548x; 1.0548x over previous
#include <cuda_runtime.h>

#define N_NODES 50000
#define N_EDGES 600000
#define N_MOL   512
#define NF      30
#define EPAIRS  (N_EDGES / 2)     // 300000, N_EDGES is even

// ---------------- scratch (device globals; no allocation) ----------------
// h layout per node (3 x float4 = 12 floats): [m0..m3][m4..m7][m8, deg, 0, 0]
__device__ float4 g_h4[(size_t)N_NODES * 3];
// packed node data (2 x float4): [px,py,pz,b0][b1,b2,0,0]
__device__ float4 g_nd[(size_t)N_NODES * 2];
__device__ float  g_w[N_EDGES];          // edge_attr[:,0] compacted (written in prep)
__device__ float  g_nodesum[N_NODES];
__device__ float  g_acc[N_MOL];
__device__ float  g_atoms[N_MOL];

#define NODE_BLOCKS ((N_NODES + 255) / 256)

__device__ __forceinline__ void atomic_add_f4(float4* p, float4 v) {
#if defined(__CUDA_ARCH__) && (__CUDA_ARCH__ >= 900)
    atomicAdd(p, v);
#else
    float* s = (float*)p;
    atomicAdd(s + 0, v.x);
    atomicAdd(s + 1, v.y);
    atomicAdd(s + 2, v.z);
    atomicAdd(s + 3, v.w);
#endif
}

__device__ __forceinline__ float inv_sqrt_deg(float d) {
    return (d > 0.0f) ? rsqrtf(fmaxf(d, 1.0f)) : 0.0f;
}

__device__ __forceinline__ void compute_ea(float x, float y, float z, float w, float* ea) {
    const float s3  = 1.7320508075688772f;
    const float s5  = 2.2360679774997896f;
    const float s15 = 3.8729833462074170f;
    float r2 = x * x + y * y + z * z;
    ea[0] = w;
    ea[1] = w * s3 * x;
    ea[2] = w * s3 * y;
    ea[3] = w * s3 * z;
    ea[4] = w * s15 * x * y;
    ea[5] = w * s15 * y * z;
    ea[6] = w * 0.5f * s5 * (3.0f * z * z - r2);
    ea[7] = w * s15 * x * z;
    ea[8] = w * 0.5f * s15 * (x * x - y * y);
}

// ---------------- kernel 0 (fused prep): zero + w-extract + b = x@V + pos pack ----------------
__global__ void k_prep(const float* __restrict__ eattr,
                       const float* __restrict__ x,
                       const float* __restrict__ pos,
                       const float* __restrict__ W1_0,
                       const float* __restrict__ W1_1,
                       const float* __restrict__ W1_2,
                       const float* __restrict__ W2_0,
                       const float* __restrict__ W2_1,
                       const float* __restrict__ W2_2) {
    __shared__ float sV[3 * NF];
    int t = threadIdx.x;
    int i = blockIdx.x * blockDim.x + t;

    // V = (W1_l @ W2_l)/sqrt(30), only in blocks that will compute b
    if (blockIdx.x < NODE_BLOCKS) {
        const float inv_s30 = 0.18257418583505536f;
        if (t < NF) {
            float acc = 0.0f;
            #pragma unroll
            for (int u = 0; u < 64; u++) acc = fmaf(W1_0[t * 64 + u], W2_0[u], acc);
            sV[t] = acc * inv_s30;
        } else if (t < 2 * NF) {
            int k = t - NF;
            float acc = 0.0f;
            #pragma unroll
            for (int u = 0; u < 24; u++) acc = fmaf(W1_1[k * 24 + u], W2_1[u], acc);
            sV[t] = acc * inv_s30;
        } else if (t < 3 * NF) {
            int k = t - 2 * NF;
            float acc = 0.0f;
            #pragma unroll
            for (int u = 0; u < 16; u++) acc = fmaf(W1_2[k * 16 + u], W2_2[u], acc);
            sV[t] = acc * inv_s30;
        }
        __syncthreads();
    }

    // compact edge weight (streams the 24 MB edge_attr once)
    if (i < N_EDGES) g_w[i] = __ldcs(eattr + (size_t)i * 10);

    // zero scratch (each array accumulated only in LATER kernels — race-free)
    if (i < N_NODES * 3) g_h4[i] = make_float4(0.f, 0.f, 0.f, 0.f);
    if (i < N_NODES) g_nodesum[i] = 0.0f;
    if (i < N_MOL)  { g_acc[i] = 0.0f; g_atoms[i] = 0.0f; }

    if (i < N_NODES) {
        // b = x @ V, packed with position
        const float* xr = x + (size_t)i * NF;
        float b0 = 0.0f, b1 = 0.0f, b2 = 0.0f;
        #pragma unroll
        for (int k = 0; k < NF; k++) {
            float xv = xr[k];
            b0 = fmaf(xv, sV[k], b0);
            b1 = fmaf(xv, sV[NF + k], b1);
            b2 = fmaf(xv, sV[2 * NF + k], b2);
        }
        float px = pos[i * 3 + 0];
        float py = pos[i * 3 + 1];
        float pz = pos[i * 3 + 2];
        g_nd[(size_t)i * 2 + 0] = make_float4(px, py, pz, b0);
        g_nd[(size_t)i * 2 + 1] = make_float4(b1, b2, 0.f, 0.f);
    }
}

// ---------------- kernel 1: edge scatter (2 edges/thread; 3 float4 atomics per edge) ----------
__global__ void k_scatter(const int2* __restrict__ esrc2,
                          const int2* __restrict__ edst2) {
    int p = blockIdx.x * blockDim.x + threadIdx.x;
    if (p >= EPAIRS) return;
    int2 sp = esrc2[p];
    int2 dp = edst2[p];
    float2 wp = *(const float2*)(g_w + 2 * p);

    // issue all independent loads up front (MLP)
    float4 a_s0 = g_nd[(size_t)sp.x * 2 + 0];
    float4 a_s1 = g_nd[(size_t)sp.x * 2 + 1];
    float4 a_d0 = g_nd[(size_t)dp.x * 2 + 0];
    float4 b_s0 = g_nd[(size_t)sp.y * 2 + 0];
    float4 b_s1 = g_nd[(size_t)sp.y * 2 + 1];
    float4 b_d0 = g_nd[(size_t)dp.y * 2 + 0];

    {
        float ea[9];
        compute_ea(a_s0.x - a_d0.x, a_s0.y - a_d0.y, a_s0.z - a_d0.z, wp.x, ea);
        float b0 = a_s0.w, b1 = a_s1.x, b2 = a_s1.y;
        float4* hp = g_h4 + (size_t)dp.x * 3;
        atomic_add_f4(hp + 0, make_float4(b0 * ea[0], b1 * ea[1], b1 * ea[2], b1 * ea[3]));
        atomic_add_f4(hp + 1, make_float4(b2 * ea[4], b2 * ea[5], b2 * ea[6], b2 * ea[7]));
        atomic_add_f4(hp + 2, make_float4(b2 * ea[8], 1.0f, 0.f, 0.f));
    }
    {
        float ea[9];
        compute_ea(b_s0.x - b_d0.x, b_s0.y - b_d0.y, b_s0.z - b_d0.z, wp.y, ea);
        float b0 = b_s0.w, b1 = b_s1.x, b2 = b_s1.y;
        float4* hp = g_h4 + (size_t)dp.y * 3;
        atomic_add_f4(hp + 0, make_float4(b0 * ea[0], b1 * ea[1], b1 * ea[2], b1 * ea[3]));
        atomic_add_f4(hp + 1, make_float4(b2 * ea[4], b2 * ea[5], b2 * ea[6], b2 * ea[7]));
        atomic_add_f4(hp + 2, make_float4(b2 * ea[8], 1.0f, 0.f, 0.f));
    }
}

// ---------------- kernel 2: edge gather + contraction (2 edges/thread; isd_src only) ----------
__global__ void k_gather(const int2* __restrict__ esrc2,
                         const int2* __restrict__ edst2) {
    int p = blockIdx.x * blockDim.x + threadIdx.x;
    if (p >= EPAIRS) return;
    int2 sp = esrc2[p];
    int2 dp = edst2[p];
    float2 wp = *(const float2*)(g_w + 2 * p);

    // issue all independent loads up front (MLP)
    float4 a_s0 = g_nd[(size_t)sp.x * 2 + 0];
    float4 a_d0 = g_nd[(size_t)dp.x * 2 + 0];
    float4 a_h0 = g_h4[(size_t)sp.x * 3 + 0];
    float4 a_h1 = g_h4[(size_t)sp.x * 3 + 1];
    float4 a_h2 = g_h4[(size_t)sp.x * 3 + 2];
    float4 b_s0 = g_nd[(size_t)sp.y * 2 + 0];
    float4 b_d0 = g_nd[(size_t)dp.y * 2 + 0];
    float4 b_h0 = g_h4[(size_t)sp.y * 3 + 0];
    float4 b_h1 = g_h4[(size_t)sp.y * 3 + 1];
    float4 b_h2 = g_h4[(size_t)sp.y * 3 + 2];

    const float inv_s3 = 0.5773502691896258f;
    const float inv_s5 = 0.4472135954999579f;
    const float sc = 0.09805806756909202f;  // 1/sqrt(104)

    {
        float ea[9];
        compute_ea(a_s0.x - a_d0.x, a_s0.y - a_d0.y, a_s0.z - a_d0.z, wp.x, ea);
        float isd_src = inv_sqrt_deg(a_h2.y);
        float t0 = a_h0.x * ea[0];
        float t1 = a_h0.y * ea[1] + a_h0.z * ea[2] + a_h0.w * ea[3];
        float t2 = a_h1.x * ea[4] + a_h1.y * ea[5] + a_h1.z * ea[6]
                 + a_h1.w * ea[7] + a_h2.x * ea[8];
        float out_e = (t0 + t1 * inv_s3 + t2 * inv_s5) * isd_src * sc;
        atomicAdd(&g_nodesum[dp.x], out_e);
    }
    {
        float ea[9];
        compute_ea(b_s0.x - b_d0.x, b_s0.y - b_d0.y, b_s0.z - b_d0.z, wp.y, ea);
        float isd_src = inv_sqrt_deg(b_h2.y);
        float t0 = b_h0.x * ea[0];
        float t1 = b_h0.y * ea[1] + b_h0.z * ea[2] + b_h0.w * ea[3];
        float t2 = b_h1.x * ea[4] + b_h1.y * ea[5] + b_h1.z * ea[6]
                 + b_h1.w * ea[7] + b_h2.x * ea[8];
        float out_e = (t0 + t1 * inv_s3 + t2 * inv_s5) * isd_src * sc;
        atomicAdd(&g_nodesum[dp.y], out_e);
    }
}

// ---------------- kernel 3: node -> molecule (warp-segmented aggregation; sorted batch) --------
__global__ void k_node_to_mol(const int* __restrict__ batch) {
    int i = blockIdx.x * blockDim.x + threadIdx.x;
    int lane = threadIdx.x & 31;
    bool valid = (i < N_NODES);
    int m = valid ? batch[i] : -1;
    float v = 0.0f, c = 0.0f;
    if (valid) {
        float isd = inv_sqrt_deg(g_h4[(size_t)i * 3 + 2].y);
        v = g_nodesum[i] * isd;
        c = 1.0f;
    }
    // segmented suffix-sum over contiguous equal-m runs (batch sorted)
    #pragma unroll
    for (int off = 1; off < 32; off <<= 1) {
        float nv = __shfl_down_sync(0xFFFFFFFFu, v, off);
        float nc = __shfl_down_sync(0xFFFFFFFFu, c, off);
        int   nm = __shfl_down_sync(0xFFFFFFFFu, m, off);
        if (lane + off < 32 && nm == m) { v += nv; c += nc; }
    }
    int pm = __shfl_up_sync(0xFFFFFFFFu, m, 1);
    bool head = valid && (lane == 0 || pm != m);
    if (head) {
        atomicAdd(&g_acc[m], v);
        atomicAdd(&g_atoms[m], c);
    }
}

// ---------------- kernel 4: finalize ----------------
__global__ void k_finalize(float* __restrict__ out) {
    int m = threadIdx.x;
    if (m < N_MOL) {
        float a = g_atoms[m];
        out[m] = g_acc[m] * ((a > 0.0f) ? rsqrtf(fmaxf(a, 1.0f)) : 0.0f);
    }
}

// ---------------- launch ----------------
extern "C" void kernel_launch(void* const* d_in, const int* in_sizes, int n_in,
                              void* d_out, int out_size) {
    (void)in_sizes; (void)n_in; (void)out_size;
    const float* pos   = (const float*)d_in[0];
    const float* x     = (const float*)d_in[1];
    const float* eattr = (const float*)d_in[2];
    const float* W1_0  = (const float*)d_in[3];
    const float* W1_1  = (const float*)d_in[4];
    const float* W1_2  = (const float*)d_in[5];
    const float* W2_0  = (const float*)d_in[6];
    const float* W2_1  = (const float*)d_in[7];
    const float* W2_2  = (const float*)d_in[8];
    const int2* esrc2  = (const int2*)d_in[9];
    const int2* edst2  = (const int2*)d_in[10];
    const int* batch   = (const int*)d_in[11];
    float* out = (float*)d_out;

    int eblocks = (N_EDGES + 255) / 256;     // prep covers edge range for w-extract
    int pblocks = (EPAIRS + 255) / 256;      // 2 edges per thread
    k_prep<<<eblocks, 256>>>(eattr, x, pos, W1_0, W1_1, W1_2, W2_0, W2_1, W2_2);
    k_scatter<<<pblocks, 256>>>(esrc2, edst2);
    k_gather<<<pblocks, 256>>>(esrc2, edst2);
    k_node_to_mol<<<(N_NODES + 255) / 256, 256>>>(batch);
    k_finalize<<<1, N_MOL>>>(out);
}